// round 17
// baseline (speedup 1.0000x reference)
#include <cuda_runtime.h>
#include <cuda_bf16.h>
#include <cstdint>

constexpr int Bc = 8, Hc = 16, Mc = 1024, Nc = 1024, Dc = 64;
constexpr int BHc = Bc * Hc;
constexpr long long OUT_ELEMS = (long long)BHc * Mc * Dc;
constexpr long long P_ELEMS   = (long long)BHc * Mc * Nc;

constexpr int MT = 32;        // M rows per CTA
constexpr int NT = 128;       // tile depth
constexpr int THREADS = 256;  // 8 warps, 3 CTAs/SM

// ---- fragment-layout scratch, uint4-packed (shared by 32 CTAs per bh) ----
// KS slot = ((nbg*4 + kc)*32 + lane) : {h0, h1, l0, l1} bf16x2 pairs (B of QK^T)
// VS slot = ((kc16*8 + db)*32 + lane): {b0h, b1h, b0l, b1l} bf16x2 pairs (B of PV, V^T layout)
__device__ uint4 KSg[(size_t)BHc * 8 * 2048];   // 32 MB
__device__ uint4 VSg[(size_t)BHc * 8 * 2048];   // 32 MB

// ---- main-kernel smem (bytes) ----
constexpr int QH_OFF = 0;        // phase 1: Q hi plane [32][72] bf16 (pitch 144B), transient
constexpr int QL_OFF = 4608;
constexpr int PH_OFF = 0;        // phase 3: P hi plane [32][144] bf16 (pitch 288B), aliases Q
constexpr int PL_OFF = 9216;     // P lo plane -> end 18432
constexpr int RED_OFF = 0;       // epilogue reduce (24576 B, aliases P planes)
constexpr int MSK_OFF = 24576;   // int[1024]
constexpr int SMEM_BYTES = 28672;

#define NEG_INF_F (-1e9f)

__device__ __forceinline__ uint32_t pack2(float a, float b) {   // a -> low half
    uint32_t r; asm("cvt.rn.bf16x2.f32 %0, %1, %2;" : "=r"(r) : "f"(b), "f"(a)); return r;
}
__device__ __forceinline__ float bfr(float x) { return __bfloat162float(__float2bfloat16_rn(x)); }
__device__ __forceinline__ void store_hilo(char* sm, int ho, int lo, uint32_t byte, float4 v) {
    uint2 h = make_uint2(pack2(v.x, v.y), pack2(v.z, v.w));
    uint2 l = make_uint2(pack2(v.x - bfr(v.x), v.y - bfr(v.y)),
                         pack2(v.z - bfr(v.z), v.w - bfr(v.w)));
    *(uint2*)(sm + ho + byte) = h;
    *(uint2*)(sm + lo + byte) = l;
}
__device__ __forceinline__ void mma_bf16(float* c, const uint32_t* a, uint32_t b0, uint32_t b1) {
    asm volatile("mma.sync.aligned.m16n8k16.row.col.f32.bf16.bf16.f32 "
        "{%0,%1,%2,%3}, {%4,%5,%6,%7}, {%8,%9}, {%0,%1,%2,%3};\n"
        : "+f"(c[0]), "+f"(c[1]), "+f"(c[2]), "+f"(c[3])
        : "r"(a[0]), "r"(a[1]), "r"(a[2]), "r"(a[3]), "r"(b0), "r"(b1));
}

// =================== prep: K/V -> packed fragment scratch ===================
__global__ __launch_bounds__(256)
void prep_kernel(const float* __restrict__ k, const float* __restrict__ v)
{
    __shared__ float KT[128 * 68];
    const int bhnt = blockIdx.x;            // bh*8 + nt
    const int bh = bhnt >> 3, nt = bhnt & 7;
    const int tid = threadIdx.x;

    // ---- K tile [n][k] -> KS ----
    {
        const float4* kg = (const float4*)(k + ((size_t)bh * Nc + nt * NT) * Dc);
        #pragma unroll
        for (int i = 0; i < 8; i++) {
            int f4 = i * 256 + tid;
            float4 val = kg[f4];
            *(float4*)(KT + (f4 >> 4) * 68 + (f4 & 15) * 4) = val;
        }
    }
    __syncthreads();
    {
        uint4* ks = KSg + (size_t)bhnt * 2048;
        #pragma unroll
        for (int i = 0; i < 8; i++) {
            int slot = i * 256 + tid;
            int l = slot & 31, idx = slot >> 5;       // idx = nbg*4 + kc
            int nbg = idx >> 2, kc = idx & 3;
            int n = nbg * 8 + (l >> 2), k0 = kc * 16 + 2 * (l & 3);
            float x0 = KT[n * 68 + k0],     x1 = KT[n * 68 + k0 + 1];
            float y0 = KT[n * 68 + k0 + 8], y1 = KT[n * 68 + k0 + 9];
            ks[slot] = make_uint4(pack2(x0, x1), pack2(y0, y1),
                                  pack2(x0 - bfr(x0), x1 - bfr(x1)),
                                  pack2(y0 - bfr(y0), y1 - bfr(y1)));
        }
    }
    __syncthreads();
    // ---- V tile [k][d] -> VS (V^T bf16 hi/lo fragments) ----
    {
        const float4* vg = (const float4*)(v + ((size_t)bh * Nc + nt * NT) * Dc);
        #pragma unroll
        for (int i = 0; i < 8; i++) {
            int f4 = i * 256 + tid;
            float4 val = vg[f4];
            *(float4*)(KT + (f4 >> 4) * 68 + (f4 & 15) * 4) = val;   // KT[k][d] pitch 68
        }
    }
    __syncthreads();
    {
        uint4* vs = VSg + (size_t)bhnt * 2048;
        #pragma unroll
        for (int i = 0; i < 8; i++) {
            int slot = i * 256 + tid;
            int l = slot & 31, idx = slot >> 5;       // idx = kc16*8 + db
            int kc16 = idx >> 3, db = idx & 7;
            int d = db * 8 + (l >> 2), k0 = kc16 * 16 + 2 * (l & 3);
            float x0 = KT[k0 * 68 + d],       x1 = KT[(k0 + 1) * 68 + d];
            float y0 = KT[(k0 + 8) * 68 + d], y1 = KT[(k0 + 9) * 68 + d];
            vs[slot] = make_uint4(pack2(x0, x1), pack2(y0, y1),
                                  pack2(x0 - bfr(x0), x1 - bfr(x1)),
                                  pack2(y0 - bfr(y0), y1 - bfr(y1)));
        }
    }
}

// =================== main kernel ===================
__global__ __launch_bounds__(THREADS, 3)
void attn_k17(const float* __restrict__ q, const int* __restrict__ mask,
              float* __restrict__ outp, float* __restrict__ pp)
{
    extern __shared__ char sm[];
    int* Msk = (int*)(sm + MSK_OFF);

    const int bh = blockIdx.x >> 5;
    const int m0 = (blockIdx.x & 31) * MT;
    const int tid = threadIdx.x, wid = tid >> 5, lane = tid & 31;
    const int g = lane >> 2, t = lane & 3;
    const float scale = 1.0f / 32.0f;   // 1/sqrt(N=1024), faithful to source bug
    float* Sbase = pp + ((size_t)bh * Mc + m0) * Nc;

    #pragma unroll
    for (int i = 0; i < Nc / THREADS; i++)
        Msk[i * THREADS + tid] = mask[(size_t)bh * Nc + i * THREADS + tid];

    {   // stage Q -> bf16 hi/lo planes (pitch 144 B), transient
        const float4* qg = (const float4*)(q + (size_t)(bh * Mc + m0) * Dc);
        #pragma unroll
        for (int i = 0; i < 2; i++) {
            int f4 = i * THREADS + tid;
            float4 val = qg[f4];
            store_hilo(sm, QH_OFF, QL_OFF, (uint32_t)((f4 >> 4) * 144 + (f4 & 15) * 8), val);
        }
    }
    __syncthreads();

    // hoist Q fragments (hi+lo) to registers
    const int mi = wid & 1, nbp = wid >> 1;
    uint32_t ah[4][4], al[4][4];
    #pragma unroll
    for (int kc = 0; kc < 4; kc++) {
        uint32_t base = (uint32_t)((mi * 16 + g) * 144 + kc * 32 + 4 * t);
        ah[kc][0] = *(uint32_t*)(sm + QH_OFF + base);
        ah[kc][1] = *(uint32_t*)(sm + QH_OFF + base + 8 * 144);
        ah[kc][2] = *(uint32_t*)(sm + QH_OFF + base + 16);
        ah[kc][3] = *(uint32_t*)(sm + QH_OFF + base + 8 * 144 + 16);
        al[kc][0] = *(uint32_t*)(sm + QL_OFF + base);
        al[kc][1] = *(uint32_t*)(sm + QL_OFF + base + 8 * 144);
        al[kc][2] = *(uint32_t*)(sm + QL_OFF + base + 16);
        al[kc][3] = *(uint32_t*)(sm + QL_OFF + base + 8 * 144 + 16);
    }
    __syncthreads();   // Q region free for phase-3 reuse

    // ============ phase 1: S = mask(scale(Q K^T)), bf16 3-term, NO syncs ============
    const uint4* ksb = KSg + (size_t)(bh * 8) * 2048;
    #pragma unroll 1
    for (int nt = 0; nt < Nc / NT; nt++) {
        const uint4* kst = ksb + nt * 2048;
        float acc[4][4] = {};
        #pragma unroll
        for (int kc = 0; kc < 4; kc++) {
            #pragma unroll
            for (int nb = 0; nb < 4; nb++) {
                uint4 kf = kst[((nbp * 4 + nb) * 4 + kc) * 32 + lane];
                mma_bf16(acc[nb], ah[kc], kf.x, kf.y);   // qh*kh
                mma_bf16(acc[nb], al[kc], kf.x, kf.y);   // ql*kh
                mma_bf16(acc[nb], ah[kc], kf.z, kf.w);   // qh*kl
            }
        }
        #pragma unroll
        for (int nb = 0; nb < 4; nb++) {
            const int m = mi * 16 + g;
            const int n = nt * NT + nbp * 32 + nb * 8 + 2 * t;
            const bool ok0 = Msk[n] != 0, ok1 = Msk[n + 1] != 0;
            *(float2*)(Sbase + (size_t)m * Nc + n) = make_float2(
                ok0 ? acc[nb][0] * scale : NEG_INF_F, ok1 ? acc[nb][1] * scale : NEG_INF_F);
            *(float2*)(Sbase + (size_t)(m + 8) * Nc + n) = make_float2(
                ok0 ? acc[nb][2] * scale : NEG_INF_F, ok1 ? acc[nb][3] * scale : NEG_INF_F);
        }
    }
    __syncthreads();

    // ============ phase 2: register softmax (rows L2-hot) ============
    #pragma unroll 1
    for (int rr = 0; rr < 4; rr++) {
        const int m = wid * 4 + rr;
        float* prow = Sbase + (size_t)m * Nc;
        float r[32], mx = NEG_INF_F;
        #pragma unroll
        for (int i = 0; i < 32; i++) { r[i] = prow[i * 32 + lane]; mx = fmaxf(mx, r[i]); }
        #pragma unroll
        for (int o = 16; o; o >>= 1) mx = fmaxf(mx, __shfl_xor_sync(0xffffffffu, mx, o));
        float s = 0.0f;
        #pragma unroll
        for (int i = 0; i < 32; i++) { r[i] = __expf(r[i] - mx); s += r[i]; }
        #pragma unroll
        for (int o = 16; o; o >>= 1) s += __shfl_xor_sync(0xffffffffu, s, o);
        const float inv = 1.0f / s;
        #pragma unroll
        for (int i = 0; i < 32; i++) prow[i * 32 + lane] = r[i] * inv;
    }
    __syncthreads();

    // ============ phase 3: out = P V, bf16 3-term, k-quarter split ============
    const int mi3 = wid & 1, kq = wid >> 1;
    const uint4* vsb = VSg + (size_t)(bh * 8) * 2048;

    float oacc[8][4] = {};
    #pragma unroll 1
    for (int nt = 0; nt < Nc / NT; nt++) {
        __syncthreads();
        {   // stage P block [32][128] -> bf16 hi/lo planes (pitch 288 B)
            #pragma unroll
            for (int i = 0; i < 4; i++) {
                int f4 = i * THREADS + tid;
                int row = f4 >> 5, c = (f4 & 31) * 4;
                float4 val = *(const float4*)(Sbase + (size_t)row * Nc + nt * NT + c);
                store_hilo(sm, PH_OFF, PL_OFF, (uint32_t)(row * 288 + c * 2), val);
            }
        }
        __syncthreads();

        const uint4* vst = vsb + nt * 2048;
        #pragma unroll
        for (int kc = 0; kc < 2; kc++) {
            const int kk = kq * 32 + kc * 16;
            const uint32_t pbase = (uint32_t)((mi3 * 16 + g) * 288 + (kk + 2 * t) * 2);
            uint32_t pah[4], pal[4];
            pah[0] = *(uint32_t*)(sm + PH_OFF + pbase);
            pah[1] = *(uint32_t*)(sm + PH_OFF + pbase + 8 * 288);
            pah[2] = *(uint32_t*)(sm + PH_OFF + pbase + 16);
            pah[3] = *(uint32_t*)(sm + PH_OFF + pbase + 8 * 288 + 16);
            pal[0] = *(uint32_t*)(sm + PL_OFF + pbase);
            pal[1] = *(uint32_t*)(sm + PL_OFF + pbase + 8 * 288);
            pal[2] = *(uint32_t*)(sm + PL_OFF + pbase + 16);
            pal[3] = *(uint32_t*)(sm + PL_OFF + pbase + 8 * 288 + 16);
            const int kc16 = kq * 2 + kc;
            #pragma unroll
            for (int db = 0; db < 8; db++) {
                uint4 vv = vst[(kc16 * 8 + db) * 32 + lane];
                mma_bf16(oacc[db], pah, vv.x, vv.y);   // ph*vh
                mma_bf16(oacc[db], pal, vv.x, vv.y);   // pl*vh
                mma_bf16(oacc[db], pah, vv.z, vv.w);   // ph*vl
            }
        }
    }
    __syncthreads();
    // k-quarter reduce through Red (aliases P planes; dead now)
    float* Red = (float*)(sm + RED_OFF);
    if (kq != 0) {
        #pragma unroll
        for (int db = 0; db < 8; db++)
            *(float4*)(&Red[((mi3 * 3 + (kq - 1)) * 8 + db) * 128 + lane * 4]) =
                make_float4(oacc[db][0], oacc[db][1], oacc[db][2], oacc[db][3]);
    }
    __syncthreads();
    if (kq == 0 && outp) {
        #pragma unroll
        for (int db = 0; db < 8; db++) {
            float4 r1 = *(float4*)(&Red[((mi3 * 3 + 0) * 8 + db) * 128 + lane * 4]);
            float4 r2 = *(float4*)(&Red[((mi3 * 3 + 1) * 8 + db) * 128 + lane * 4]);
            float4 r3 = *(float4*)(&Red[((mi3 * 3 + 2) * 8 + db) * 128 + lane * 4]);
            const int m = mi3 * 16 + g;
            float* ob = outp + ((size_t)bh * Mc + m0 + m) * Dc + db * 8 + 2 * t;
            *(float2*)ob = make_float2(oacc[db][0] + r1.x + r2.x + r3.x,
                                       oacc[db][1] + r1.y + r2.y + r3.y);
            *(float2*)(ob + 8 * Dc) = make_float2(oacc[db][2] + r1.z + r2.z + r3.z,
                                                  oacc[db][3] + r1.w + r2.w + r3.w);
        }
    }
}

extern "C" void kernel_launch(void* const* d_in, const int* in_sizes, int n_in,
                              void* d_out, int out_size)
{
    const float* q    = (const float*)d_in[0];
    const float* k    = (const float*)d_in[1];
    const float* v    = (const float*)d_in[2];
    const int*   mask = (const int*)d_in[3];
    float* outp = nullptr;
    float* pp   = nullptr;
    long long osz = (long long)out_size;
    if (osz >= OUT_ELEMS + P_ELEMS) { outp = (float*)d_out; pp = (float*)d_out + OUT_ELEMS; }
    else                            { pp = (float*)d_out; }

    prep_kernel<<<BHc * 8, 256>>>(k, v);
    cudaFuncSetAttribute(attn_k17, cudaFuncAttributeMaxDynamicSharedMemorySize, SMEM_BYTES);
    attn_k17<<<BHc * (Mc / MT), THREADS, SMEM_BYTES>>>(q, mask, outp, pp);
}